// round 10
// baseline (speedup 1.0000x reference)
#include <cuda_runtime.h>
#include <math.h>
#include <stdint.h>

#define LVOX 4096
#define NBATCH 4
#define NB 8          // (branch, batch) pairs
#define MAXN 32       // max neighbors per voxel (analytic bound: <= 27)
#define CPB 4         // channels per phase-B block
#define TPB_A 256
#define ABLK 16       // phase-A blocks per nb
#define TPB_B 512
#define PF 4          // list prefetch depth

// Scratch: static device globals (no allocation allowed)
__device__ unsigned char  g_cntb[NB][LVOX];        // cnt(nb,l) as byte
__device__ unsigned short g_nbr[NB][MAXN][LVOX];   // PRE-SWIZZLED idx m'=((m&3)<<10)|(m>>2)
__device__ int            g_partial[NB][ABLK];     // per-block pair counts
__device__ double         g_num[NB];
__device__ unsigned int   g_done;

// ───────────────────────── Phase A ─────────────────────────
__global__ void k_phaseA(const float* __restrict__ cq, const float* __restrict__ ck) {
    int nb  = blockIdx.y;
    int l   = blockIdx.x * TPB_A + threadIdx.x;
    int tid = threadIdx.x;
    int br = nb >> 2;
    int n  = nb & 3;
    int qb = br ? (3 - n) : n;     // flipped q-batch for branch 1

    if (blockIdx.x == 0 && tid == 0) {
        g_num[nb] = 0.0;           // consumed only after kernel boundary
        if (nb == 0) g_done = 0u;
    }

    float q0 = cq[qb*6+0], q1 = cq[qb*6+1], q2 = cq[qb*6+2];
    float bq0 = (cq[qb*6+3] - q0) * (1.0f/16.0f);
    float bq1 = (cq[qb*6+4] - q1) * (1.0f/16.0f);
    float bq2 = (cq[qb*6+5] - q2) * (1.0f/16.0f);
    float k0 = ck[n*6+0], k1 = ck[n*6+1], k2 = ck[n*6+2];
    float bk0 = (ck[n*6+3] - k0) * (1.0f/16.0f);
    float bk1 = (ck[n*6+4] - k1) * (1.0f/16.0f);
    float bk2 = (ck[n*6+5] - k2) * (1.0f/16.0f);

    // max_diag uses UNFLIPPED diag_q[n], diag_k[n]
    float a0 = (cq[n*6+3] - cq[n*6+0]) * (1.0f/16.0f);
    float a1 = (cq[n*6+4] - cq[n*6+1]) * (1.0f/16.0f);
    float a2 = (cq[n*6+5] - cq[n*6+2]) * (1.0f/16.0f);
    float diagq = sqrtf((a0*a0 + a1*a1) + a2*a2);
    float diagk = sqrtf((bk0*bk0 + bk1*bk1) + bk2*bk2);
    float md = fmaxf(diagq, diagk);
    float R  = 0.5f * md;

    int i  = l >> 8;
    int j  = (l >> 4) & 15;
    int kz = l & 15;
    float cx = fmaf((float)i  + 0.5f, bq0, q0);
    float cy = fmaf((float)j  + 0.5f, bq1, q1);
    float cz = fmaf((float)kz + 0.5f, bq2, q2);

    int xlo = max(0,  (int)floorf((cx - R - k0) / bk0 - 0.5f));
    int xhi = min(15, (int)ceilf ((cx + R - k0) / bk0 - 0.5f));
    int ylo = max(0,  (int)floorf((cy - R - k1) / bk1 - 0.5f));
    int yhi = min(15, (int)ceilf ((cy + R - k1) / bk1 - 0.5f));
    int zlo = max(0,  (int)floorf((cz - R - k2) / bk2 - 0.5f));
    int zhi = min(15, (int)ceilf ((cz + R - k2) / bk2 - 0.5f));

    int cnt = 0;
    for (int jx = xlo; jx <= xhi; jx++) {
        float dx = cx - fmaf((float)jx + 0.5f, bk0, k0);
        for (int jy = ylo; jy <= yhi; jy++) {
            float dy = cy - fmaf((float)jy + 0.5f, bk1, k1);
            for (int jz = zlo; jz <= zhi; jz++) {
                float dz = cz - fmaf((float)jz + 0.5f, bk2, k2);
                float d2 = dx*dx + dy*dy + dz*dz;
                // Exact reference semantics: sqrt then divide then compare
                if (sqrtf(d2) / md < 0.5f) {
                    if (cnt < MAXN) {
                        int m = jx*256 + jy*16 + jz;
                        // pre-swizzle for quartered smem layout in phase B
                        g_nbr[nb][cnt][l] = (unsigned short)(((m & 3) << 10) | (m >> 2));
                    }
                    cnt++;
                }
            }
        }
    }
    if (cnt > MAXN) cnt = MAXN;
    g_cntb[nb][l] = (unsigned char)cnt;

    __shared__ int red[TPB_A / 32];
    int mc = cnt;
    for (int o = 16; o; o >>= 1) mc += __shfl_down_sync(0xFFFFFFFFu, mc, o);
    if ((tid & 31) == 0) red[tid >> 5] = mc;
    __syncthreads();
    if (tid == 0) {
        int s = 0;
        for (int w = 0; w < TPB_A / 32; w++) s += red[w];
        g_partial[nb][blockIdx.x] = s;
    }
}

// ───────────────────────── Phase B (+ fused finalize) ─────────────────────────
// Block = (channel chunk, batch n, l-half). Each thread handles ONE group of 4
// consecutive l's. Counts + first-PF list entries are prefetched BEFORE the
// staging sync so their latency overlaps the k-tile staging.
__global__ void __launch_bounds__(TPB_B, 3)
k_phaseB(const float* __restrict__ q, const float* __restrict__ k,
         float* __restrict__ out, int nblocks) {
    int cchunk = blockIdx.x;   // 0..79
    int n      = blockIdx.y;   // 0..3
    int half   = blockIdx.z;   // 0..1
    int c0     = cchunk * CPB;
    extern __shared__ float4 kk4[];   // [4][1024] quartered transposed tile = 64KB
    int tid = threadIdx.x;

    int nb0 = n, nb1 = 4 + n;
    int G   = half * (LVOX / 8) + tid;   // one group per thread (1024 groups total)
    int l4  = G * 4;

    // ── Prefetch metadata (independent of smem) ──
    uchar4 cv0 = ((const uchar4*)g_cntb[nb0])[G];
    uchar4 cv1 = ((const uchar4*)g_cntb[nb1])[G];
    ushort4 pf0[PF], pf1[PF];
#pragma unroll
    for (int t = 0; t < PF; t++) {
        pf0[t] = *(const ushort4*)&g_nbr[nb0][t][l4];
        pf1[t] = *(const ushort4*)&g_nbr[nb1][t][l4];
    }

    // ── Stage k tile: float4 loads per channel, conflict-free quartered stores ──
    {
        const float4* kc0 = (const float4*)(k + ((size_t)n * 320 + c0 + 0) * (size_t)LVOX);
        const float4* kc1 = (const float4*)(k + ((size_t)n * 320 + c0 + 1) * (size_t)LVOX);
        const float4* kc2 = (const float4*)(k + ((size_t)n * 320 + c0 + 2) * (size_t)LVOX);
        const float4* kc3 = (const float4*)(k + ((size_t)n * 320 + c0 + 3) * (size_t)LVOX);
        for (int g = tid; g < LVOX / 4; g += TPB_B) {   // 2 passes
            float4 a = kc0[g], b = kc1[g], c = kc2[g], d = kc3[g];
            kk4[g]        = make_float4(a.x, b.x, c.x, d.x);
            kk4[1024 + g] = make_float4(a.y, b.y, c.y, d.y);
            kk4[2048 + g] = make_float4(a.z, b.z, c.z, d.z);
            kk4[3072 + g] = make_float4(a.w, b.w, c.w, d.w);
        }
    }
    __syncthreads();

    const float* qn = q + ((size_t)n       * 320 + c0) * (size_t)LVOX;
    const float* qf = q + ((size_t)(3 - n) * 320 + c0) * (size_t)LVOX;

    float acc0[4] = {0.f, 0.f, 0.f, 0.f};
    float acc1[4] = {0.f, 0.f, 0.f, 0.f};

    // ---- branch 0 ----
    {
        int cm = max(max((int)cv0.x, (int)cv0.y), max((int)cv0.z, (int)cv0.w));
        float4 s0 = {0,0,0,0}, s1 = {0,0,0,0}, s2 = {0,0,0,0}, s3 = {0,0,0,0};
#pragma unroll
        for (int t = 0; t < PF; t++) {
            if (t < (int)cv0.x) { float4 kv = kk4[pf0[t].x & 4095]; s0.x += kv.x; s0.y += kv.y; s0.z += kv.z; s0.w += kv.w; }
            if (t < (int)cv0.y) { float4 kv = kk4[pf0[t].y & 4095]; s1.x += kv.x; s1.y += kv.y; s1.z += kv.z; s1.w += kv.w; }
            if (t < (int)cv0.z) { float4 kv = kk4[pf0[t].z & 4095]; s2.x += kv.x; s2.y += kv.y; s2.z += kv.z; s2.w += kv.w; }
            if (t < (int)cv0.w) { float4 kv = kk4[pf0[t].w & 4095]; s3.x += kv.x; s3.y += kv.y; s3.z += kv.z; s3.w += kv.w; }
        }
        for (int t = PF; t < cm; t++) {
            ushort4 mm = *(const ushort4*)&g_nbr[nb0][t][l4];
            if (t < (int)cv0.x) { float4 kv = kk4[mm.x]; s0.x += kv.x; s0.y += kv.y; s0.z += kv.z; s0.w += kv.w; }
            if (t < (int)cv0.y) { float4 kv = kk4[mm.y]; s1.x += kv.x; s1.y += kv.y; s1.z += kv.z; s1.w += kv.w; }
            if (t < (int)cv0.z) { float4 kv = kk4[mm.z]; s2.x += kv.x; s2.y += kv.y; s2.z += kv.z; s2.w += kv.w; }
            if (t < (int)cv0.w) { float4 kv = kk4[mm.w]; s3.x += kv.x; s3.y += kv.y; s3.z += kv.z; s3.w += kv.w; }
        }
        if (cm) {
            float4 qv;
            qv = ((const float4*)(qn + 0 * LVOX))[G];
            acc0[0] += qv.x*s0.x + qv.y*s1.x + qv.z*s2.x + qv.w*s3.x;
            qv = ((const float4*)(qn + 1 * LVOX))[G];
            acc0[1] += qv.x*s0.y + qv.y*s1.y + qv.z*s2.y + qv.w*s3.y;
            qv = ((const float4*)(qn + 2 * LVOX))[G];
            acc0[2] += qv.x*s0.z + qv.y*s1.z + qv.z*s2.z + qv.w*s3.z;
            qv = ((const float4*)(qn + 3 * LVOX))[G];
            acc0[3] += qv.x*s0.w + qv.y*s1.w + qv.z*s2.w + qv.w*s3.w;
        }
    }
    // ---- branch 1 ----
    {
        int cm = max(max((int)cv1.x, (int)cv1.y), max((int)cv1.z, (int)cv1.w));
        float4 s0 = {0,0,0,0}, s1 = {0,0,0,0}, s2 = {0,0,0,0}, s3 = {0,0,0,0};
#pragma unroll
        for (int t = 0; t < PF; t++) {
            if (t < (int)cv1.x) { float4 kv = kk4[pf1[t].x & 4095]; s0.x += kv.x; s0.y += kv.y; s0.z += kv.z; s0.w += kv.w; }
            if (t < (int)cv1.y) { float4 kv = kk4[pf1[t].y & 4095]; s1.x += kv.x; s1.y += kv.y; s1.z += kv.z; s1.w += kv.w; }
            if (t < (int)cv1.z) { float4 kv = kk4[pf1[t].z & 4095]; s2.x += kv.x; s2.y += kv.y; s2.z += kv.z; s2.w += kv.w; }
            if (t < (int)cv1.w) { float4 kv = kk4[pf1[t].w & 4095]; s3.x += kv.x; s3.y += kv.y; s3.z += kv.z; s3.w += kv.w; }
        }
        for (int t = PF; t < cm; t++) {
            ushort4 mm = *(const ushort4*)&g_nbr[nb1][t][l4];
            if (t < (int)cv1.x) { float4 kv = kk4[mm.x]; s0.x += kv.x; s0.y += kv.y; s0.z += kv.z; s0.w += kv.w; }
            if (t < (int)cv1.y) { float4 kv = kk4[mm.y]; s1.x += kv.x; s1.y += kv.y; s1.z += kv.z; s1.w += kv.w; }
            if (t < (int)cv1.z) { float4 kv = kk4[mm.z]; s2.x += kv.x; s2.y += kv.y; s2.z += kv.z; s2.w += kv.w; }
            if (t < (int)cv1.w) { float4 kv = kk4[mm.w]; s3.x += kv.x; s3.y += kv.y; s3.z += kv.z; s3.w += kv.w; }
        }
        if (cm) {
            float4 qv;
            qv = ((const float4*)(qf + 0 * LVOX))[G];
            acc1[0] += qv.x*s0.x + qv.y*s1.x + qv.z*s2.x + qv.w*s3.x;
            qv = ((const float4*)(qf + 1 * LVOX))[G];
            acc1[1] += qv.x*s0.y + qv.y*s1.y + qv.z*s2.y + qv.w*s3.y;
            qv = ((const float4*)(qf + 2 * LVOX))[G];
            acc1[2] += qv.x*s0.z + qv.y*s1.z + qv.z*s2.z + qv.w*s3.z;
            qv = ((const float4*)(qf + 3 * LVOX))[G];
            acc1[3] += qv.x*s0.w + qv.y*s1.w + qv.z*s2.w + qv.w*s3.w;
        }
    }

    double t0 = (double)acc0[0] + (double)acc0[1] + (double)acc0[2] + (double)acc0[3];
    double t1 = (double)acc1[0] + (double)acc1[1] + (double)acc1[2] + (double)acc1[3];
    for (int o = 16; o; o >>= 1) {
        t0 += __shfl_down_sync(0xFFFFFFFFu, t0, o);
        t1 += __shfl_down_sync(0xFFFFFFFFu, t1, o);
    }
    __shared__ double red0[TPB_B / 32], red1[TPB_B / 32];
    if ((tid & 31) == 0) { red0[tid >> 5] = t0; red1[tid >> 5] = t1; }
    __syncthreads();
    if (tid == 0) {
        double s0 = 0.0, s1 = 0.0;
        for (int w = 0; w < TPB_B / 32; w++) { s0 += red0[w]; s1 += red1[w]; }
        atomicAdd(&g_num[nb0], s0);
        atomicAdd(&g_num[nb1], s1);
        __threadfence();
        unsigned int ticket = atomicAdd(&g_done, 1u);
        if (ticket == (unsigned int)(nblocks - 1)) {
            double a = 0.0, b = 0.0;
            for (int m = 0; m < NBATCH; m++) {
                int tot0 = 0, tot1 = 0;
                for (int w = 0; w < ABLK; w++) {
                    tot0 += g_partial[m][w];
                    tot1 += g_partial[4 + m][w];
                }
                a += g_num[m]     / ((double)tot0 + 1e-6);
                b += g_num[4 + m] / ((double)tot1 + 1e-6);
            }
            out[0] = (float)(-2.0 * (a / 4.0) - 2.0 * (b / 4.0));
        }
    }
}

extern "C" void kernel_launch(void* const* d_in, const int* in_sizes, int n_in,
                              void* d_out, int out_size) {
    const float* q  = (const float*)d_in[0];
    const float* k  = (const float*)d_in[1];
    const float* cq = (const float*)d_in[2];
    const float* ck = (const float*)d_in[3];

    (void)cudaFuncSetAttribute(k_phaseB, cudaFuncAttributeMaxDynamicSharedMemorySize,
                               LVOX * (int)sizeof(float4));

    dim3 ga(ABLK, NB);
    k_phaseA<<<ga, TPB_A>>>(cq, ck);
    dim3 gb(320 / CPB, NBATCH, 2);   // 640 blocks: chunk x batch x l-half
    k_phaseB<<<gb, TPB_B, LVOX * (int)sizeof(float4)>>>(q, k, (float*)d_out, 640);
}

// round 15
// speedup vs baseline: 1.2343x; 1.2343x over previous
#include <cuda_runtime.h>
#include <math.h>
#include <stdint.h>

#define LVOX 4096
#define NBATCH 4
#define NB 8          // (branch, batch) pairs
#define MAXN 32       // max neighbors per voxel (analytic bound: <= 27)
#define CPB 4         // channels per phase-B block
#define TPB_A 256
#define ABLK 16       // phase-A blocks per nb
#define TPB_B 512

// Scratch: static device globals (no allocation allowed)
__device__ unsigned char  g_cntb[NB][LVOX];        // cnt(nb,l) as byte
__device__ unsigned short g_nbr[NB][MAXN][LVOX];   // PRE-SWIZZLED idx m'=((m&3)<<10)|(m>>2)
__device__ int            g_partial[NB][ABLK];     // per-block pair counts
__device__ double         g_num[NB];
__device__ unsigned int   g_done;

// ───────────────────────── Phase A ─────────────────────────
__global__ void k_phaseA(const float* __restrict__ cq, const float* __restrict__ ck) {
    int nb  = blockIdx.y;
    int l   = blockIdx.x * TPB_A + threadIdx.x;
    int tid = threadIdx.x;
    int br = nb >> 2;
    int n  = nb & 3;
    int qb = br ? (3 - n) : n;     // flipped q-batch for branch 1

    if (blockIdx.x == 0 && tid == 0) {
        g_num[nb] = 0.0;           // consumed only after kernel boundary
        if (nb == 0) g_done = 0u;
    }

    float q0 = cq[qb*6+0], q1 = cq[qb*6+1], q2 = cq[qb*6+2];
    float bq0 = (cq[qb*6+3] - q0) * (1.0f/16.0f);
    float bq1 = (cq[qb*6+4] - q1) * (1.0f/16.0f);
    float bq2 = (cq[qb*6+5] - q2) * (1.0f/16.0f);
    float k0 = ck[n*6+0], k1 = ck[n*6+1], k2 = ck[n*6+2];
    float bk0 = (ck[n*6+3] - k0) * (1.0f/16.0f);
    float bk1 = (ck[n*6+4] - k1) * (1.0f/16.0f);
    float bk2 = (ck[n*6+5] - k2) * (1.0f/16.0f);

    // max_diag uses UNFLIPPED diag_q[n], diag_k[n]
    float a0 = (cq[n*6+3] - cq[n*6+0]) * (1.0f/16.0f);
    float a1 = (cq[n*6+4] - cq[n*6+1]) * (1.0f/16.0f);
    float a2 = (cq[n*6+5] - cq[n*6+2]) * (1.0f/16.0f);
    float diagq = sqrtf((a0*a0 + a1*a1) + a2*a2);
    float diagk = sqrtf((bk0*bk0 + bk1*bk1) + bk2*bk2);
    float md = fmaxf(diagq, diagk);
    float R  = 0.5f * md;

    int i  = l >> 8;
    int j  = (l >> 4) & 15;
    int kz = l & 15;
    float cx = fmaf((float)i  + 0.5f, bq0, q0);
    float cy = fmaf((float)j  + 0.5f, bq1, q1);
    float cz = fmaf((float)kz + 0.5f, bq2, q2);

    int xlo = max(0,  (int)floorf((cx - R - k0) / bk0 - 0.5f));
    int xhi = min(15, (int)ceilf ((cx + R - k0) / bk0 - 0.5f));
    int ylo = max(0,  (int)floorf((cy - R - k1) / bk1 - 0.5f));
    int yhi = min(15, (int)ceilf ((cy + R - k1) / bk1 - 0.5f));
    int zlo = max(0,  (int)floorf((cz - R - k2) / bk2 - 0.5f));
    int zhi = min(15, (int)ceilf ((cz + R - k2) / bk2 - 0.5f));

    int cnt = 0;
    for (int jx = xlo; jx <= xhi; jx++) {
        float dx = cx - fmaf((float)jx + 0.5f, bk0, k0);
        for (int jy = ylo; jy <= yhi; jy++) {
            float dy = cy - fmaf((float)jy + 0.5f, bk1, k1);
            for (int jz = zlo; jz <= zhi; jz++) {
                float dz = cz - fmaf((float)jz + 0.5f, bk2, k2);
                float d2 = dx*dx + dy*dy + dz*dz;
                // Exact reference semantics: sqrt then divide then compare
                if (sqrtf(d2) / md < 0.5f) {
                    if (cnt < MAXN) {
                        int m = jx*256 + jy*16 + jz;
                        // pre-swizzle for quartered smem layout in phase B
                        g_nbr[nb][cnt][l] = (unsigned short)(((m & 3) << 10) | (m >> 2));
                    }
                    cnt++;
                }
            }
        }
    }
    if (cnt > MAXN) cnt = MAXN;
    g_cntb[nb][l] = (unsigned char)cnt;

    __shared__ int red[TPB_A / 32];
    int mc = cnt;
    for (int o = 16; o; o >>= 1) mc += __shfl_down_sync(0xFFFFFFFFu, mc, o);
    if ((tid & 31) == 0) red[tid >> 5] = mc;
    __syncthreads();
    if (tid == 0) {
        int s = 0;
        for (int w = 0; w < TPB_A / 32; w++) s += red[w];
        g_partial[nb][blockIdx.x] = s;
    }
}

// ───────────────────────── Phase B (+ fused finalize) ─────────────────────────
// Block = (channel chunk, batch n). One wave of 320 blocks @ 3 CTAs/SM.
// smem: 64KB quartered transposed k tile + 8KB count bytes (both branches).
// Counts read via LDS (29cy) instead of L2 LDG (~240cy) -> shorter dep chain.
__global__ void __launch_bounds__(TPB_B, 3)
k_phaseB(const float* __restrict__ q, const float* __restrict__ k,
         float* __restrict__ out, int nblocks) {
    int cchunk = blockIdx.x;   // 0..79
    int n      = blockIdx.y;   // 0..3
    int c0     = cchunk * CPB;
    extern __shared__ char sm_raw[];
    float4* kk4 = (float4*)sm_raw;                               // 64KB
    unsigned char* scnt0 = (unsigned char*)(sm_raw + 65536);     // 4KB
    unsigned char* scnt1 = scnt0 + LVOX;                         // 4KB
    int tid = threadIdx.x;
    int nb0 = n, nb1 = 4 + n;

    // ── Copy count bytes to smem (coalesced uint4; overlaps k staging) ──
    {
        const uint4* s0 = (const uint4*)g_cntb[nb0];
        const uint4* s1 = (const uint4*)g_cntb[nb1];
        if (tid < 256)       ((uint4*)scnt0)[tid]       = s0[tid];
        else if (tid < 512)  ((uint4*)scnt1)[tid - 256] = s1[tid - 256];
    }

    // ── Stage k tile: float4 loads per channel, conflict-free quartered stores ──
    {
        const float4* kc0 = (const float4*)(k + ((size_t)n * 320 + c0 + 0) * (size_t)LVOX);
        const float4* kc1 = (const float4*)(k + ((size_t)n * 320 + c0 + 1) * (size_t)LVOX);
        const float4* kc2 = (const float4*)(k + ((size_t)n * 320 + c0 + 2) * (size_t)LVOX);
        const float4* kc3 = (const float4*)(k + ((size_t)n * 320 + c0 + 3) * (size_t)LVOX);
        for (int g = tid; g < LVOX / 4; g += TPB_B) {   // 2 passes
            float4 a = kc0[g], b = kc1[g], c = kc2[g], d = kc3[g];
            kk4[g]        = make_float4(a.x, b.x, c.x, d.x);
            kk4[1024 + g] = make_float4(a.y, b.y, c.y, d.y);
            kk4[2048 + g] = make_float4(a.z, b.z, c.z, d.z);
            kk4[3072 + g] = make_float4(a.w, b.w, c.w, d.w);
        }
    }
    __syncthreads();

    const float* qn = q + ((size_t)n       * 320 + c0) * (size_t)LVOX;
    const float* qf = q + ((size_t)(3 - n) * 320 + c0) * (size_t)LVOX;

    float acc0[4] = {0.f, 0.f, 0.f, 0.f};
    float acc1[4] = {0.f, 0.f, 0.f, 0.f};

#pragma unroll
    for (int gi = 0; gi < 2; gi++) {
        int G  = gi * TPB_B + tid;   // two groups of 4 l's per thread
        int l4 = G * 4;

        // Counts from smem (cheap), q loads unconditional (hoistable)
        uchar4 cv0 = *(const uchar4*)&scnt0[l4];
        uchar4 cv1 = *(const uchar4*)&scnt1[l4];

        // ---- branch 0 ----
        {
            int cm = max(max((int)cv0.x, (int)cv0.y), max((int)cv0.z, (int)cv0.w));
            float4 s0 = {0,0,0,0}, s1 = {0,0,0,0}, s2 = {0,0,0,0}, s3 = {0,0,0,0};
            for (int t = 0; t < cm; t++) {
                ushort4 mm = *(const ushort4*)&g_nbr[nb0][t][l4];
                if (t < (int)cv0.x) { float4 kv = kk4[mm.x]; s0.x += kv.x; s0.y += kv.y; s0.z += kv.z; s0.w += kv.w; }
                if (t < (int)cv0.y) { float4 kv = kk4[mm.y]; s1.x += kv.x; s1.y += kv.y; s1.z += kv.z; s1.w += kv.w; }
                if (t < (int)cv0.z) { float4 kv = kk4[mm.z]; s2.x += kv.x; s2.y += kv.y; s2.z += kv.z; s2.w += kv.w; }
                if (t < (int)cv0.w) { float4 kv = kk4[mm.w]; s3.x += kv.x; s3.y += kv.y; s3.z += kv.z; s3.w += kv.w; }
            }
            float4 qv;
            qv = ((const float4*)(qn + 0 * LVOX))[G];
            acc0[0] += qv.x*s0.x + qv.y*s1.x + qv.z*s2.x + qv.w*s3.x;
            qv = ((const float4*)(qn + 1 * LVOX))[G];
            acc0[1] += qv.x*s0.y + qv.y*s1.y + qv.z*s2.y + qv.w*s3.y;
            qv = ((const float4*)(qn + 2 * LVOX))[G];
            acc0[2] += qv.x*s0.z + qv.y*s1.z + qv.z*s2.z + qv.w*s3.z;
            qv = ((const float4*)(qn + 3 * LVOX))[G];
            acc0[3] += qv.x*s0.w + qv.y*s1.w + qv.z*s2.w + qv.w*s3.w;
        }
        // ---- branch 1 ----
        {
            int cm = max(max((int)cv1.x, (int)cv1.y), max((int)cv1.z, (int)cv1.w));
            float4 s0 = {0,0,0,0}, s1 = {0,0,0,0}, s2 = {0,0,0,0}, s3 = {0,0,0,0};
            for (int t = 0; t < cm; t++) {
                ushort4 mm = *(const ushort4*)&g_nbr[nb1][t][l4];
                if (t < (int)cv1.x) { float4 kv = kk4[mm.x]; s0.x += kv.x; s0.y += kv.y; s0.z += kv.z; s0.w += kv.w; }
                if (t < (int)cv1.y) { float4 kv = kk4[mm.y]; s1.x += kv.x; s1.y += kv.y; s1.z += kv.z; s1.w += kv.w; }
                if (t < (int)cv1.z) { float4 kv = kk4[mm.z]; s2.x += kv.x; s2.y += kv.y; s2.z += kv.z; s2.w += kv.w; }
                if (t < (int)cv1.w) { float4 kv = kk4[mm.w]; s3.x += kv.x; s3.y += kv.y; s3.z += kv.z; s3.w += kv.w; }
            }
            float4 qv;
            qv = ((const float4*)(qf + 0 * LVOX))[G];
            acc1[0] += qv.x*s0.x + qv.y*s1.x + qv.z*s2.x + qv.w*s3.x;
            qv = ((const float4*)(qf + 1 * LVOX))[G];
            acc1[1] += qv.x*s0.y + qv.y*s1.y + qv.z*s2.y + qv.w*s3.y;
            qv = ((const float4*)(qf + 2 * LVOX))[G];
            acc1[2] += qv.x*s0.z + qv.y*s1.z + qv.z*s2.z + qv.w*s3.z;
            qv = ((const float4*)(qf + 3 * LVOX))[G];
            acc1[3] += qv.x*s0.w + qv.y*s1.w + qv.z*s2.w + qv.w*s3.w;
        }
    }

    double t0 = (double)acc0[0] + (double)acc0[1] + (double)acc0[2] + (double)acc0[3];
    double t1 = (double)acc1[0] + (double)acc1[1] + (double)acc1[2] + (double)acc1[3];
    for (int o = 16; o; o >>= 1) {
        t0 += __shfl_down_sync(0xFFFFFFFFu, t0, o);
        t1 += __shfl_down_sync(0xFFFFFFFFu, t1, o);
    }
    __shared__ double red0[TPB_B / 32], red1[TPB_B / 32];
    if ((tid & 31) == 0) { red0[tid >> 5] = t0; red1[tid >> 5] = t1; }
    __syncthreads();
    if (tid == 0) {
        double s0 = 0.0, s1 = 0.0;
        for (int w = 0; w < TPB_B / 32; w++) { s0 += red0[w]; s1 += red1[w]; }
        atomicAdd(&g_num[nb0], s0);
        atomicAdd(&g_num[nb1], s1);
        __threadfence();
        unsigned int ticket = atomicAdd(&g_done, 1u);
        if (ticket == (unsigned int)(nblocks - 1)) {
            double a = 0.0, b = 0.0;
            for (int m = 0; m < NBATCH; m++) {
                int tot0 = 0, tot1 = 0;
                for (int w = 0; w < ABLK; w++) {
                    tot0 += g_partial[m][w];
                    tot1 += g_partial[4 + m][w];
                }
                a += g_num[m]     / ((double)tot0 + 1e-6);
                b += g_num[4 + m] / ((double)tot1 + 1e-6);
            }
            out[0] = (float)(-2.0 * (a / 4.0) - 2.0 * (b / 4.0));
        }
    }
}

extern "C" void kernel_launch(void* const* d_in, const int* in_sizes, int n_in,
                              void* d_out, int out_size) {
    const float* q  = (const float*)d_in[0];
    const float* k  = (const float*)d_in[1];
    const float* cq = (const float*)d_in[2];
    const float* ck = (const float*)d_in[3];

    const int smemB = 65536 + 2 * LVOX;   // k tile + count bytes = 73728
    (void)cudaFuncSetAttribute(k_phaseB, cudaFuncAttributeMaxDynamicSharedMemorySize,
                               smemB);

    dim3 ga(ABLK, NB);
    k_phaseA<<<ga, TPB_A>>>(cq, ck);
    dim3 gb(320 / CPB, NBATCH);   // 320 blocks: one clean wave @ 3 CTAs/SM
    k_phaseB<<<gb, TPB_B, smemB>>>(q, k, (float*)d_out, 320);
}